// round 7
// baseline (speedup 1.0000x reference)
#include <cuda_runtime.h>
#include <math.h>
#include <stdint.h>

#define NPT 60000
#define EPSBN 1e-5f

__device__ float g_coords[NPT * 3];
__device__ float g_q   [NPT * 128];
__device__ float g_qh  [NPT * 128];
__device__ float g_Kf  [NPT * 128];
__device__ float g_Vf  [NPT * 128];
__device__ float g_qk  [(size_t)NPT * 1024];
__device__ float g_att [NPT * 128];
__device__ float g_S   [(size_t)NPT * 1024];
__device__ float g_att2[NPT * 128];
__device__ float g_x1  [NPT * 128];
__device__ float g_x1n [NPT * 128];
__device__ float g_ff1 [(size_t)NPT * 512];
__device__ float g_x2  [NPT * 128];
__device__ float g_x2n [NPT * 128];
__device__ float g_y   [NPT * 128];
__device__ float g_part[128 * 256];
__device__ float g_sums[256];

// ---- coords + q = features + relu(coords @ qpos_w.T + b) ----
__global__ void coords_q_kernel(const int* __restrict__ ind, const float* __restrict__ f,
                                const float* __restrict__ qpw, const float* __restrict__ qpb,
                                float* __restrict__ coords, float* __restrict__ q, int n) {
    int idx = blockIdx.x * 256 + threadIdx.x;
    int row = idx >> 7, c = idx & 127;
    if (row >= n) return;
    float cx = ((float)ind[row*4+3] + 0.5f) * 0.1f - 40.0f;
    float cy = ((float)ind[row*4+2] + 0.5f) * 0.1f - 40.0f;
    float cz = ((float)ind[row*4+1] + 0.5f) * 0.2f - 3.0f;
    if (c == 0) { coords[row*3+0]=cx; coords[row*3+1]=cy; coords[row*3+2]=cz; }
    float p = cx*qpw[c*3+0] + cy*qpw[c*3+1] + cz*qpw[c*3+2] + qpb[c];
    q[idx] = f[idx] + fmaxf(p, 0.0f);
}

// ---- GEMM: Y = [relu]( X @ W^T + bias [+ res] ); W: [cout,cin] ----
__global__ void gemm_kernel(const float* __restrict__ X, const float* __restrict__ W,
                            const float* __restrict__ bias, float* __restrict__ Y,
                            const float* __restrict__ res, int doRelu,
                            int n, int cin, int cout) {
    extern __shared__ float sm[];
    float* Xs = sm;               // 64x128
    float* Ws = sm + 64 * 128;    // 128x129 transposed
    int row0 = blockIdx.x * 64, j0 = blockIdx.y * 128;
    int tid = threadIdx.x, tx = tid & 31, ty = tid >> 5;
    float acc[8][4];
#pragma unroll
    for (int r = 0; r < 8; r++) { acc[r][0]=acc[r][1]=acc[r][2]=acc[r][3]=0.f; }

    for (int c0 = 0; c0 < cin; c0 += 128) {
#pragma unroll
        for (int i = 0; i < 8; i++) {
            int l = tid + 256*i, r = l >> 5, c4 = l & 31;
            int row = row0 + r;
            float4 v = make_float4(0.f,0.f,0.f,0.f);
            if (row < n) v = *(const float4*)(X + (size_t)row*cin + c0 + (c4<<2));
            *(float4*)(Xs + r*128 + (c4<<2)) = v;
        }
#pragma unroll 8
        for (int i = 0; i < 64; i++) {
            int l = tid + 256*i, j = l >> 7, c = l & 127;
            Ws[c*129 + j] = W[(size_t)(j0+j)*cin + c0 + c];
        }
        __syncthreads();
#pragma unroll 2
        for (int c = 0; c < 128; ++c) {
            float w0 = Ws[c*129+tx],    w1 = Ws[c*129+tx+32];
            float w2 = Ws[c*129+tx+64], w3 = Ws[c*129+tx+96];
#pragma unroll
            for (int r = 0; r < 8; ++r) {
                float xv = Xs[(ty*8+r)*128 + c];
                acc[r][0]=fmaf(xv,w0,acc[r][0]); acc[r][1]=fmaf(xv,w1,acc[r][1]);
                acc[r][2]=fmaf(xv,w2,acc[r][2]); acc[r][3]=fmaf(xv,w3,acc[r][3]);
            }
        }
        __syncthreads();
    }
    float b0=bias[j0+tx], b1=bias[j0+tx+32], b2=bias[j0+tx+64], b3=bias[j0+tx+96];
#pragma unroll
    for (int r = 0; r < 8; ++r) {
        int row = row0 + ty*8 + r;
        if (row >= n) break;
        float v0=acc[r][0]+b0, v1=acc[r][1]+b1, v2=acc[r][2]+b2, v3=acc[r][3]+b3;
        size_t base = (size_t)row*cout + j0;
        if (res) { v0+=res[base+tx]; v1+=res[base+tx+32]; v2+=res[base+tx+64]; v3+=res[base+tx+96]; }
        if (doRelu) { v0=fmaxf(v0,0.f); v1=fmaxf(v1,0.f); v2=fmaxf(v2,0.f); v3=fmaxf(v3,0.f); }
        Y[base+tx]=v0; Y[base+tx+32]=v1; Y[base+tx+64]=v2; Y[base+tx+96]=v3;
    }
}

// ---- qk[n][h*128+c] = sum_d qh[n][h*16+d] * wk[h*16+d][c] ----
__global__ void qk_kernel(const float* __restrict__ qh, const float* __restrict__ wk,
                          float* __restrict__ qk, int n) {
    extern __shared__ float sm[];
    float* wks = sm;            // 128x128
    float* qr0 = sm + 16384;
    float* qr1 = sm + 16384 + 128;
    int tid = threadIdx.x;
#pragma unroll 8
    for (int i = 0; i < 128; i++) wks[tid + 128*i] = wk[tid + 128*i];
    __syncthreads();
    int r0 = blockIdx.x * 64;
    for (int r = 0; r < 64; r += 2) {
        int rowA = r0 + r, rowB = rowA + 1;
        if (rowA >= n) break;
        int rowBl = rowB < n ? rowB : rowA;
        qr0[tid] = qh[(size_t)rowA*128 + tid];
        qr1[tid] = qh[(size_t)rowBl*128 + tid];
        __syncthreads();
#pragma unroll
        for (int h = 0; h < 8; h++) {
            float a0 = 0.f, a1 = 0.f;
#pragma unroll
            for (int d = 0; d < 16; d++) {
                float w = wks[(h*16+d)*128 + tid];
                a0 = fmaf(qr0[h*16+d], w, a0);
                a1 = fmaf(qr1[h*16+d], w, a1);
            }
            qk[(size_t)rowA*1024 + h*128 + tid] = a0;
            if (rowB < n) qk[(size_t)rowB*1024 + h*128 + tid] = a1;
        }
        __syncthreads();
    }
}

// ---- attention core: 2 queries per block (groups of 128 threads) ----
__global__ __launch_bounds__(256) void attn_kernel(
    const int* __restrict__ key_indices, const float* __restrict__ coords,
    const float* __restrict__ qh_g, const float* __restrict__ qk_g,
    const float* __restrict__ Kf, const float* __restrict__ Vf,
    const float* __restrict__ kpw, const float* __restrict__ kpb,
    float* __restrict__ att_g, float* __restrict__ S_g, int n) {

    __shared__ float relupos[2][32 * 129];
    __shared__ float qks[2][1024];
    __shared__ float qhs[2][128];
    __shared__ float sc[2][8 * 33];
    __shared__ float rel[2][32 * 4];
    __shared__ int   gidx[2][32];

    int grp = threadIdx.x >> 7;
    int t   = threadIdx.x & 127;
    int nq  = blockIdx.x * 2 + grp;
    if (nq >= n) nq = n - 1;          // duplicate work, no divergence

    if (t < 32) {
        int ki = key_indices[nq*32 + t];
        gidx[grp][t] = ki;
        int g = ki < 0 ? 0 : ki;
        float qx = coords[nq*3+0], qy = coords[nq*3+1], qz = coords[nq*3+2];
        rel[grp][t*4+0] = coords[g*3+0] - qx;
        rel[grp][t*4+1] = coords[g*3+1] - qy;
        rel[grp][t*4+2] = coords[g*3+2] - qz;
    }
    qhs[grp][t] = qh_g[(size_t)nq*128 + t];
#pragma unroll
    for (int h = 0; h < 8; h++)
        qks[grp][h*128 + t] = qk_g[(size_t)nq*1024 + h*128 + t];
    __syncthreads();

    {   // relupos[k][c] = relu(rel[k] . kpos_w[c] + kpos_b[c])
        float kw0=kpw[t*3+0], kw1=kpw[t*3+1], kw2=kpw[t*3+2], kb=kpb[t];
#pragma unroll 4
        for (int k = 0; k < 32; k++) {
            float rx=rel[grp][k*4+0], ry=rel[grp][k*4+1], rz=rel[grp][k*4+2];
            relupos[grp][k*129+t] = fmaxf(fmaf(rx,kw0,fmaf(ry,kw1,fmaf(rz,kw2,kb))), 0.f);
        }
    }
    __syncthreads();

    {   // scores: thread -> (k, head pair)
        int k = t & 31, hp = t >> 5, h0 = hp*2, h1 = h0+1;
        int ki = gidx[grp][k];
        int g = ki < 0 ? 0 : ki;
        const float4* kf4 = reinterpret_cast<const float4*>(Kf + (size_t)g*128 + h0*16);
        float a0 = 0.f, a1 = 0.f;
#pragma unroll
        for (int i = 0; i < 4; i++) {
            float4 kv = kf4[i];
            a0 += kv.x*qhs[grp][h0*16+i*4+0] + kv.y*qhs[grp][h0*16+i*4+1]
                + kv.z*qhs[grp][h0*16+i*4+2] + kv.w*qhs[grp][h0*16+i*4+3];
        }
#pragma unroll
        for (int i = 0; i < 4; i++) {
            float4 kv = kf4[4+i];
            a1 += kv.x*qhs[grp][h1*16+i*4+0] + kv.y*qhs[grp][h1*16+i*4+1]
                + kv.z*qhs[grp][h1*16+i*4+2] + kv.w*qhs[grp][h1*16+i*4+3];
        }
        const float* rp = &relupos[grp][k*129];
        const float* q0 = &qks[grp][h0*128];
        const float* q1 = q0 + 128;
        float b0 = 0.f, b1 = 0.f;
#pragma unroll 4
        for (int c = 0; c < 128; c++) {
            float rv = rp[c];
            b0 = fmaf(rv, q0[c], b0);
            b1 = fmaf(rv, q1[c], b1);
        }
        float s0 = (a0 + b0) * 0.25f;   // 1/sqrt(DH=16)
        float s1 = (a1 + b1) * 0.25f;
        if (ki < 0) { s0 = -3.0e38f; s1 = -3.0e38f; }
        sc[grp][h0*33 + k] = s0;
        sc[grp][h1*33 + k] = s1;
    }
    __syncthreads();

    if (t < 8) {    // softmax per head
        float m = -3.4e38f;
#pragma unroll 4
        for (int k = 0; k < 32; k++) m = fmaxf(m, sc[grp][t*33+k]);
        float ssum = 0.f;
#pragma unroll 4
        for (int k = 0; k < 32; k++) {
            float e = expf(sc[grp][t*33+k] - m);
            sc[grp][t*33+k] = e; ssum += e;
        }
        float inv = 1.0f / ssum;
#pragma unroll 4
        for (int k = 0; k < 32; k++) sc[grp][t*33+k] *= inv;
    }
    __syncthreads();

    {   // V accumulation + s_h accumulation
        int h = t >> 4;
        float att = 0.f;
        float s[8];
#pragma unroll
        for (int i = 0; i < 8; i++) s[i] = 0.f;
#pragma unroll 2
        for (int k = 0; k < 32; k++) {
            int ki = gidx[grp][k];
            int g = ki < 0 ? 0 : ki;
            float v   = Vf[(size_t)g*128 + t];
            float rpv = relupos[grp][k*129 + t];
            att = fmaf(sc[grp][h*33+k], v, att);
#pragma unroll
            for (int hh = 0; hh < 8; hh++)
                s[hh] = fmaf(sc[grp][hh*33+k], rpv, s[hh]);
        }
        att_g[(size_t)nq*128 + t] = att;
#pragma unroll
        for (int hh = 0; hh < 8; hh++)
            S_g[(size_t)nq*1024 + hh*128 + t] = s[hh];
    }
}

// ---- att2[n][c] = att[n][c] + S[n][h(c)][:] . wv[c][:] ----
__global__ void attpos_kernel(const float* __restrict__ S, const float* __restrict__ att,
                              const float* __restrict__ wv, float* __restrict__ att2, int n) {
    extern __shared__ float sm[];
    float* wvT = sm;              // [cin][cout] pad 129
    float* ss  = sm + 128*129;    // [8][128]
    int tid = threadIdx.x;
#pragma unroll 8
    for (int i = 0; i < 128; i++) {
        int l = tid + 128*i, j = l >> 7, c = l & 127;
        wvT[c*129 + j] = wv[l];
    }
    __syncthreads();
    int r0 = blockIdx.x * 64, h = tid >> 4;
    for (int r = 0; r < 64; r++) {
        int row = r0 + r;
        if (row >= n) break;
#pragma unroll
        for (int i = 0; i < 8; i++)
            ss[i*128 + tid] = S[(size_t)row*1024 + i*128 + tid];
        __syncthreads();
        float a = 0.f;
        const float* sh = &ss[h*128];
#pragma unroll 4
        for (int c = 0; c < 128; c++) a = fmaf(sh[c], wvT[c*129 + tid], a);
        att2[(size_t)row*128 + tid] = att[(size_t)row*128 + tid] + a;
        __syncthreads();
    }
}

// ---- BN: deterministic two-stage stats ----
__global__ void bn_stats_kernel(const float* __restrict__ X, float* __restrict__ part, int n) {
    int c = threadIdx.x, r0 = blockIdx.x * 512;
    float s = 0.f, s2 = 0.f;
    for (int r = 0; r < 512; r++) {
        int row = r0 + r;
        if (row >= n) break;
        float v = X[(size_t)row*128 + c];
        s += v; s2 = fmaf(v, v, s2);
    }
    part[blockIdx.x*256 + c]       = s;
    part[blockIdx.x*256 + 128 + c] = s2;
}

__global__ void bn_reduce_kernel(const float* __restrict__ part, float* __restrict__ sums, int nb) {
    int c = threadIdx.x;   // 0..255
    float a = 0.f;
    for (int b = 0; b < nb; b++) a += part[b*256 + c];
    sums[c] = a;
}

__global__ void bn_apply_kernel(const float* __restrict__ X, const float* __restrict__ sums,
                                const float* __restrict__ g, const float* __restrict__ b,
                                float* __restrict__ Y, int n, int doRelu) {
    int idx = blockIdx.x * 256 + threadIdx.x;
    int c = idx & 127;
    if ((idx >> 7) >= n) return;
    float invn = 1.0f / (float)n;
    float mean = sums[c] * invn;
    float var  = sums[128 + c] * invn - mean * mean;
    float scl  = rsqrtf(var + EPSBN) * g[c];
    float v = (X[idx] - mean) * scl + b[c];
    Y[idx] = doRelu ? fmaxf(v, 0.f) : v;
}

// ---- host ----
static void launch_gemm(const float* X, const float* W, const float* b, float* Y,
                        const float* res, int relu, int n, int cin, int cout) {
    dim3 grid((n + 63) / 64, cout / 128);
    gemm_kernel<<<grid, 256, 64*128*4 + 128*129*4>>>(X, W, b, Y, res, relu, n, cin, cout);
}

extern "C" void kernel_launch(void* const* d_in, const int* in_sizes, int n_in,
                              void* d_out, int out_size) {
    const float* features = (const float*)d_in[0];
    const int*   indices  = (const int*)  d_in[1];
    const int*   key_idx  = (const int*)  d_in[2];
    const float* ipw      = (const float*)d_in[3];
    const float* ipb      = (const float*)d_in[4];
    const float* out_w    = (const float*)d_in[5];
    const float* out_b    = (const float*)d_in[6];
    const float* qpos_w   = (const float*)d_in[7];
    const float* qpos_b   = (const float*)d_in[8];
    const float* kpos_w   = (const float*)d_in[9];
    const float* kpos_b   = (const float*)d_in[10];
    const float* n1g      = (const float*)d_in[11];
    const float* n1b      = (const float*)d_in[12];
    const float* n2g      = (const float*)d_in[13];
    const float* n2b      = (const float*)d_in[14];
    const float* l1w      = (const float*)d_in[15];
    const float* l1b      = (const float*)d_in[16];
    const float* l2w      = (const float*)d_in[17];
    const float* l2b      = (const float*)d_in[18];
    const float* ow       = (const float*)d_in[19];
    const float* ob       = (const float*)d_in[20];
    const float* bog      = (const float*)d_in[21];
    const float* bob      = (const float*)d_in[22];
    float* out = (float*)d_out;

    int n = in_sizes[0] / 128;

    float *coords,*q,*qh,*Kf,*Vf,*qk,*att,*S,*att2,*x1,*x1n,*ff1,*x2,*x2n,*y,*part,*sums;
    cudaGetSymbolAddress((void**)&coords, g_coords);
    cudaGetSymbolAddress((void**)&q,    g_q);
    cudaGetSymbolAddress((void**)&qh,   g_qh);
    cudaGetSymbolAddress((void**)&Kf,   g_Kf);
    cudaGetSymbolAddress((void**)&Vf,   g_Vf);
    cudaGetSymbolAddress((void**)&qk,   g_qk);
    cudaGetSymbolAddress((void**)&att,  g_att);
    cudaGetSymbolAddress((void**)&S,    g_S);
    cudaGetSymbolAddress((void**)&att2, g_att2);
    cudaGetSymbolAddress((void**)&x1,   g_x1);
    cudaGetSymbolAddress((void**)&x1n,  g_x1n);
    cudaGetSymbolAddress((void**)&ff1,  g_ff1);
    cudaGetSymbolAddress((void**)&x2,   g_x2);
    cudaGetSymbolAddress((void**)&x2n,  g_x2n);
    cudaGetSymbolAddress((void**)&y,    g_y);
    cudaGetSymbolAddress((void**)&part, g_part);
    cudaGetSymbolAddress((void**)&sums, g_sums);

    cudaFuncSetAttribute(gemm_kernel,   cudaFuncAttributeMaxDynamicSharedMemorySize, 64*128*4 + 128*129*4);
    cudaFuncSetAttribute(qk_kernel,     cudaFuncAttributeMaxDynamicSharedMemorySize, 16384*4 + 256*4);
    cudaFuncSetAttribute(attpos_kernel, cudaFuncAttributeMaxDynamicSharedMemorySize, 128*129*4 + 1024*4);

    const float* wq = ipw;
    const float* wk = ipw + 128*128;
    const float* wv = ipw + 2*128*128;
    const float* bq = ipb;
    const float* bk = ipb + 128;
    const float* bv = ipb + 256;

    int nb_rows = (n + 63) / 64;
    int nb_pts  = (n * 128 + 255) / 256;
    int nb_bn   = (n + 511) / 512;

    coords_q_kernel<<<nb_pts, 256>>>(indices, features, qpos_w, qpos_b, coords, q, n);

    launch_gemm(q,        wq, bq, qh, nullptr, 0, n, 128, 128);
    launch_gemm(features, wk, bk, Kf, nullptr, 0, n, 128, 128);
    launch_gemm(features, wv, bv, Vf, nullptr, 0, n, 128, 128);

    qk_kernel<<<nb_rows, 128, 16384*4 + 256*4>>>(qh, wk, qk, n);

    attn_kernel<<<(n + 1) / 2, 256>>>(key_idx, coords, qh, qk, Kf, Vf,
                                      kpos_w, kpos_b, att, S, n);

    attpos_kernel<<<nb_rows, 128, 128*129*4 + 1024*4>>>(S, att, wv, att2, n);

    launch_gemm(att2, out_w, out_b, x1, features, 0, n, 128, 128);

    bn_stats_kernel<<<nb_bn, 128>>>(x1, part, n);
    bn_reduce_kernel<<<1, 256>>>(part, sums, nb_bn);
    bn_apply_kernel<<<nb_pts, 256>>>(x1, sums, n1g, n1b, x1n, n, 0);

    launch_gemm(x1n, l1w, l1b, ff1, nullptr, 1, n, 128, 512);
    launch_gemm(ff1, l2w, l2b, x2, x1n,     0, n, 512, 128);

    bn_stats_kernel<<<nb_bn, 128>>>(x2, part, n);
    bn_reduce_kernel<<<1, 256>>>(part, sums, nb_bn);
    bn_apply_kernel<<<nb_pts, 256>>>(x2, sums, n2g, n2b, x2n, n, 0);

    launch_gemm(x2n, ow, ob, y, nullptr, 0, n, 128, 128);

    bn_stats_kernel<<<nb_bn, 128>>>(y, part, n);
    bn_reduce_kernel<<<1, 256>>>(part, sums, nb_bn);
    bn_apply_kernel<<<nb_pts, 256>>>(y, sums, bog, bob, out, n, 1);
}